// round 16
// baseline (speedup 1.0000x reference)
#include <cuda_runtime.h>
#include <cuda_fp16.h>
#include <math.h>
#include <float.h>
#include <stdint.h>

#define NMAX 100000
#define EMAX 400000
#define ETOTMAX (EMAX + NMAX)
#define GMAX 4096
#define FMAX 256

// ---------------- scratch ----------------
__device__ __half g_hA[NMAX * FMAX];
__device__ __half g_hB[NMAX * FMAX];
__device__ __half g_hC[NMAX * FMAX];
__device__ __half g_hX[NMAX * 64];
__device__ __half g_Wh[64*256 + 256*256 + 256*256 + 256*128];
__device__ float g_esrc[NMAX * 4];
__device__ float g_edst[NMAX * 4];
__device__ int g_rowptr[NMAX + 1];
__device__ int g_fill[NMAX];
__device__ int g_col[ETOTMAX];
__device__ int g_blksum[512];
__device__ int g_gstart[GMAX + 1];

// ================= helpers =================
__device__ __forceinline__ uint32_t smem_u32(const void* p) {
    uint32_t a;
    asm("{ .reg .u64 t; cvta.to.shared.u64 t, %1; cvt.u32.u64 %0, t; }" : "=r"(a) : "l"(p));
    return a;
}
__device__ __forceinline__ void ldsm_x4(uint32_t* r, uint32_t addr) {
    asm volatile("ldmatrix.sync.aligned.m8n8.x4.shared.b16 {%0,%1,%2,%3}, [%4];"
                 : "=r"(r[0]), "=r"(r[1]), "=r"(r[2]), "=r"(r[3]) : "r"(addr));
}
__device__ __forceinline__ void ldsm_x4_t(uint32_t* r, uint32_t addr) {
    asm volatile("ldmatrix.sync.aligned.m8n8.x4.trans.shared.b16 {%0,%1,%2,%3}, [%4];"
                 : "=r"(r[0]), "=r"(r[1]), "=r"(r[2]), "=r"(r[3]) : "r"(addr));
}
__device__ __forceinline__ void mma_fp16(float* c, const uint32_t* a, const uint32_t* b) {
    asm volatile(
        "mma.sync.aligned.m16n8k16.row.col.f32.f16.f16.f32 "
        "{%0,%1,%2,%3}, {%4,%5,%6,%7}, {%8,%9}, {%0,%1,%2,%3};"
        : "+f"(c[0]), "+f"(c[1]), "+f"(c[2]), "+f"(c[3])
        : "r"(a[0]), "r"(a[1]), "r"(a[2]), "r"(a[3]), "r"(b[0]), "r"(b[1]));
}
__device__ __forceinline__ void cp16z(uint32_t s, const void* g, bool ok) {
    int sz = ok ? 16 : 0;
    asm volatile("cp.async.cg.shared.global [%0], [%1], 16, %2;" :: "r"(s), "l"(g), "r"(sz));
}
__device__ __forceinline__ void cp_commit() { asm volatile("cp.async.commit_group;"); }
template<int W> __device__ __forceinline__ void cp_wait() {
    asm volatile("cp.async.wait_group %0;" :: "n"(W));
}

// ================= fp32 -> fp16 conversion =================
__global__ void f2h_kernel(const float* __restrict__ in, __half* __restrict__ out, int n4) {
    int t = blockIdx.x * blockDim.x + threadIdx.x;
    if (t >= n4) return;
    float4 v = *(const float4*)(in + t * 4);
    __half2 a = __floats2half2_rn(v.x, v.y);
    __half2 b = __floats2half2_rn(v.z, v.w);
    *(uint2*)(out + t * 4) = make_uint2(*(uint32_t*)&a, *(uint32_t*)&b);
}
__global__ void wconv_kernel(const float* __restrict__ W0, const float* __restrict__ W1,
                             const float* __restrict__ W2, const float* __restrict__ W3,
                             __half* __restrict__ out) {
    int t = blockIdx.x * blockDim.x + threadIdx.x;
    if (t >= 45056) return;
    const float* src;
    int idx;
    if (t < 4096) { src = W0; idx = t; }
    else if (t < 20480) { src = W1; idx = t - 4096; }
    else if (t < 36864) { src = W2; idx = t - 20480; }
    else { src = W3; idx = t - 36864; }
    float4 v = *(const float4*)(src + idx * 4);
    __half2 a = __floats2half2_rn(v.x, v.y);
    __half2 b = __floats2half2_rn(v.z, v.w);
    *(uint2*)(out + t * 4) = make_uint2(*(uint32_t*)&a, *(uint32_t*)&b);
}

// ================= CSR build =================
__global__ void count_edges_kernel(const int* __restrict__ ei, int* __restrict__ cnt, int E) {
    int t = blockIdx.x * blockDim.x + threadIdx.x;
    if (t < E) atomicAdd(&cnt[ei[E + t]], 1);
}
__global__ void scan_block_kernel(const int* __restrict__ in, int* __restrict__ out,
                                  int* __restrict__ blksum, int n) {
    __shared__ int wsum[8];
    int t = threadIdx.x, blk = blockIdx.x;
    int base = blk * 1024 + t * 4;
    int v0 = (base + 0 < n) ? in[base + 0] : 0;
    int v1 = (base + 1 < n) ? in[base + 1] : 0;
    int v2 = (base + 2 < n) ? in[base + 2] : 0;
    int v3 = (base + 3 < n) ? in[base + 3] : 0;
    int tsum = v0 + v1 + v2 + v3;
    int lane = t & 31, w = t >> 5;
    int x = tsum;
    #pragma unroll
    for (int o = 1; o < 32; o <<= 1) {
        int y = __shfl_up_sync(0xffffffffu, x, o);
        if (lane >= o) x += y;
    }
    if (lane == 31) wsum[w] = x;
    __syncthreads();
    if (t < 8) {
        int y = wsum[t];
        #pragma unroll
        for (int o = 1; o < 8; o <<= 1) {
            int z = __shfl_up_sync(0xffu, y, o);
            if (t >= o) y += z;
        }
        wsum[t] = y;
    }
    __syncthreads();
    int woff = (w > 0) ? wsum[w - 1] : 0;
    int excl = woff + x - tsum;
    if (base + 0 < n) out[base + 0] = excl;
    if (base + 1 < n) out[base + 1] = excl + v0;
    if (base + 2 < n) out[base + 2] = excl + v0 + v1;
    if (base + 3 < n) out[base + 3] = excl + v0 + v1 + v2;
    if (t == 255) blksum[blk] = wsum[7];
}
__global__ void scan_sums_kernel(int* __restrict__ blksum, int nb) {
    __shared__ int sh[512];
    int t = threadIdx.x;
    int v = (t < nb) ? blksum[t] : 0;
    sh[t] = v;
    __syncthreads();
    for (int o = 1; o < 256; o <<= 1) {
        int y = (t >= o) ? sh[t - o] : 0;
        __syncthreads();
        sh[t] += y;
        __syncthreads();
    }
    if (t < nb) blksum[t] = sh[t] - v;
}
__global__ void add_off_fill_kernel(int* __restrict__ out, const int* __restrict__ blksum,
                                    int* __restrict__ fill, int n, int tail_val) {
    int t = blockIdx.x * blockDim.x + threadIdx.x;
    if (t < n) {
        int v = out[t] + blksum[t >> 10] + t;
        out[t] = v;
        fill[t] = v;
    }
    if (t == 0) out[n] = tail_val;
}
__global__ void fill_kernel(const int* __restrict__ ei, int* __restrict__ fill,
                            int* __restrict__ col, int E, int N) {
    int t = blockIdx.x * blockDim.x + threadIdx.x;
    int Etot = E + N;
    if (t >= Etot) return;
    int s, d;
    if (t < E) { s = ei[t]; d = ei[E + t]; } else { s = d = t - E; }
    int pos = atomicAdd(&fill[d], 1);
    col[pos] = s;
}
__global__ void gstart_kernel(const int* __restrict__ batch, int* __restrict__ gstart,
                              int N, int G) {
    int n = blockIdx.x * blockDim.x + threadIdx.x;
    if (n > N) return;
    int b = (n < N) ? batch[n] : G;
    int pb = (n > 0) ? batch[n - 1] : -1;
    for (int g = pb + 1; g <= b; g++) gstart[g] = n;
}

// ================= FP16 mma GEMM (cp.async 3-stage) + fused score epilogue ====
#define A_STRIDE 40
#define B_STRIDE 136
#define A_STAGE_BYTES (128 * A_STRIDE * 2)
#define B_STAGE_BYTES (32 * B_STRIDE * 2)
__global__ void __launch_bounds__(256, 2)
gemm_fp16_scores_kernel(const __half* __restrict__ A, const __half* __restrict__ B,
                        __half* __restrict__ C, int M, int K, int Ncol,
                        const float* __restrict__ a_s, const float* __restrict__ a_d,
                        float* __restrict__ esrc, float* __restrict__ edst,
                        int H, int Chead, int exclusive) {
    __shared__ __align__(16) __half sA[3][128 * A_STRIDE];
    __shared__ __align__(16) __half sB[3][32 * B_STRIDE];
    __shared__ float sred_ps[128], sred_pd[128];

    const int tid = threadIdx.x;
    const int bm = blockIdx.y * 128;
    const int bn = blockIdx.x * 128;
    const int warp = tid >> 5, lane = tid & 31;
    const int g = lane >> 2, tg = lane & 3;
    const int warp_m = (warp & 3) * 32;
    const int warp_n = (warp >> 2) * 64;

    const int a0 = tid, a1 = tid + 256;
    const int ar0 = a0 >> 2, ac0 = (a0 & 3) * 8;
    const int ar1 = a1 >> 2, ac1 = (a1 & 3) * 8;
    const bool aok0 = (bm + ar0) < M, aok1 = (bm + ar1) < M;
    const int br0 = a0 >> 4, bc0 = (a0 & 15) * 8;
    const int br1 = a1 >> 4, bc1 = (a1 & 15) * 8;

    const uint32_t sA_u = smem_u32(sA);
    const uint32_t sB_u = smem_u32(sB);
    const uint32_t aS0 = sA_u + (ar0 * A_STRIDE + ac0) * 2;
    const uint32_t aS1 = sA_u + (ar1 * A_STRIDE + ac1) * 2;
    const uint32_t bS0 = sB_u + (br0 * B_STRIDE + bc0) * 2;
    const uint32_t bS1 = sB_u + (br1 * B_STRIDE + bc1) * 2;

    const __half* Ag0 = A + (size_t)(bm + ar0) * K + ac0;
    const __half* Ag1 = A + (size_t)(bm + ar1) * K + ac1;
    const __half* Bg0 = B + (size_t)br0 * Ncol + bn + bc0;
    const __half* Bg1 = B + (size_t)br1 * Ncol + bn + bc1;

    const int nT = K >> 5;

    #define ISSUE_TILE(t_, st_) do { \
        int koff_ = (t_) * 32; \
        uint32_t ao_ = (st_) * (uint32_t)A_STAGE_BYTES; \
        uint32_t bo_ = (st_) * (uint32_t)B_STAGE_BYTES; \
        cp16z(aS0 + ao_, Ag0 + koff_, aok0); \
        cp16z(aS1 + ao_, Ag1 + koff_, aok1); \
        cp16z(bS0 + bo_, Bg0 + (size_t)koff_ * Ncol, true); \
        cp16z(bS1 + bo_, Bg1 + (size_t)koff_ * Ncol, true); \
        cp_commit(); \
    } while (0)

    ISSUE_TILE(0, 0);
    if (nT > 1) ISSUE_TILE(1, 1);

    float acc[2][8][4];
    #pragma unroll
    for (int mt = 0; mt < 2; mt++)
        #pragma unroll
        for (int nt = 0; nt < 8; nt++)
            #pragma unroll
            for (int r = 0; r < 4; r++) acc[mt][nt][r] = 0.f;

    const uint32_t a_frag0 = sA_u + ((warp_m + (lane & 15)) * A_STRIDE + (lane >> 4) * 8) * 2;
    const uint32_t b_frag0 = sB_u + ((((lane >> 3) & 1) * 8 + (lane & 7)) * B_STRIDE
                                     + warp_n + (lane >> 4) * 8) * 2;

    int stage = 0;
    for (int t = 0; t < nT; t++) {
        if (t + 2 < nT) {
            ISSUE_TILE(t + 2, (stage + 2) % 3);
            cp_wait<2>();
        } else if (t + 1 < nT) {
            cp_wait<1>();
        } else {
            cp_wait<0>();
        }
        __syncthreads();

        const uint32_t aoff = stage * (uint32_t)A_STAGE_BYTES;
        const uint32_t boff = stage * (uint32_t)B_STAGE_BYTES;
        #pragma unroll
        for (int kk = 0; kk < 2; kk++) {
            uint32_t afr[2][4], bfr[8][2];
            #pragma unroll
            for (int mt = 0; mt < 2; mt++) {
                ldsm_x4(afr[mt], a_frag0 + aoff + (mt * 16 * A_STRIDE + kk * 16) * 2);
            }
            #pragma unroll
            for (int p = 0; p < 4; p++) {
                uint32_t r[4];
                ldsm_x4_t(r, b_frag0 + boff + (kk * 16 * B_STRIDE + p * 16) * 2);
                bfr[2 * p][0] = r[0]; bfr[2 * p][1] = r[1];
                bfr[2 * p + 1][0] = r[2]; bfr[2 * p + 1][1] = r[3];
            }
            #pragma unroll
            for (int mt = 0; mt < 2; mt++)
                #pragma unroll
                for (int nt = 0; nt < 8; nt++)
                    mma_fp16(acc[mt][nt], afr[mt], bfr[nt]);
        }
        __syncthreads();
        stage = (stage + 1) % 3;
    }
    #undef ISSUE_TILE

    const int hh = (bn + warp_n) / Chead;
    #pragma unroll
    for (int mt = 0; mt < 2; mt++) {
        int r0 = bm + warp_m + mt * 16 + g;
        int r1 = r0 + 8;
        float ps0 = 0.f, pd0 = 0.f, ps1 = 0.f, pd1 = 0.f;
        #pragma unroll
        for (int nt = 0; nt < 8; nt++) {
            int c = bn + warp_n + nt * 8 + 2 * tg;
            float asv0 = a_s[c], asv1 = a_s[c + 1];
            float adv0 = a_d[c], adv1 = a_d[c + 1];
            ps0 += acc[mt][nt][0] * asv0 + acc[mt][nt][1] * asv1;
            pd0 += acc[mt][nt][0] * adv0 + acc[mt][nt][1] * adv1;
            ps1 += acc[mt][nt][2] * asv0 + acc[mt][nt][3] * asv1;
            pd1 += acc[mt][nt][2] * adv0 + acc[mt][nt][3] * adv1;
            if (r0 < M) *(__half2*)(C + (size_t)r0 * Ncol + c) = __floats2half2_rn(acc[mt][nt][0], acc[mt][nt][1]);
            if (r1 < M) *(__half2*)(C + (size_t)r1 * Ncol + c) = __floats2half2_rn(acc[mt][nt][2], acc[mt][nt][3]);
        }
        #pragma unroll
        for (int o = 1; o < 4; o <<= 1) {
            ps0 += __shfl_xor_sync(0xffffffffu, ps0, o);
            pd0 += __shfl_xor_sync(0xffffffffu, pd0, o);
            ps1 += __shfl_xor_sync(0xffffffffu, ps1, o);
            pd1 += __shfl_xor_sync(0xffffffffu, pd1, o);
        }
        if (exclusive) {
            if (tg == 0) {
                if (r0 < M) { esrc[r0 * H + hh] = ps0; edst[r0 * H + hh] = pd0; }
                if (r1 < M) { esrc[r1 * H + hh] = ps1; edst[r1 * H + hh] = pd1; }
            }
        } else {
            if (tg == 0 && warp < 4) {
                sred_ps[r0 - bm] = ps0; sred_pd[r0 - bm] = pd0;
                sred_ps[r1 - bm] = ps1; sred_pd[r1 - bm] = pd1;
            }
            __syncthreads();
            if (tg == 0 && warp >= 4) {
                if (r0 < M) {
                    esrc[r0 * H + hh] = ps0 + sred_ps[r0 - bm];
                    edst[r0 * H + hh] = pd0 + sred_pd[r0 - bm];
                }
                if (r1 < M) {
                    esrc[r1 * H + hh] = ps1 + sred_ps[r1 - bm];
                    edst[r1 * H + hh] = pd1 + sred_pd[r1 - bm];
                }
            }
            __syncthreads();
        }
    }
}

// ================= fused gather (branch-free fast path over CAP) ==============
template<int H, int C>
__global__ void gat_gather_kernel(const __half* __restrict__ h,
                                  const float* __restrict__ es, const float* __restrict__ ed,
                                  const int* __restrict__ rowptr, const int* __restrict__ col,
                                  const float* __restrict__ bias, __half* __restrict__ out,
                                  int N, int do_elu) {
    constexpr int F = H * C;
    constexpr int CAP = 64;
    constexpr int NW = 8;
    __shared__ float shex[NW][CAP * H];
    __shared__ int   shsrc[NW][CAP];
    const int w = threadIdx.x >> 5, lane = threadIdx.x & 31;
    const int d = blockIdx.x * NW + w;
    if (d >= N) return;
    const int start = rowptr[d];
    const int deg = rowptr[d + 1] - start;

    float edv[H];
    #pragma unroll
    for (int hh = 0; hh < H; hh++) edv[hh] = ed[d * H + hh];

    // pass 1: exp scores + denom (smem-cache first CAP edges)
    float den[H];
    #pragma unroll
    for (int hh = 0; hh < H; hh++) den[hh] = 0.f;
    for (int i0 = 0; i0 < deg; i0 += 32) {
        int i = i0 + lane;
        if (i < deg) {
            int s = col[start + i];
            if (i < CAP) shsrc[w][i] = s;
            float esv[H];
            if (H == 4) {
                float4 e4 = *(const float4*)(es + s * 4);
                esv[0] = e4.x; esv[1] = e4.y; esv[2] = e4.z; esv[3] = e4.w;
            } else {
                #pragma unroll
                for (int hh = 0; hh < H; hh++) esv[hh] = es[s * H + hh];
            }
            #pragma unroll
            for (int hh = 0; hh < H; hh++) {
                float v = esv[hh] + edv[hh];
                v = (v > 0.f) ? v : 0.2f * v;
                float ex = expf(v);
                if (i < CAP) shex[w][i * H + hh] = ex;
                den[hh] += ex;
            }
        }
    }
    float inv[H];
    #pragma unroll
    for (int hh = 0; hh < H; hh++) {
        #pragma unroll
        for (int o = 16; o; o >>= 1) den[hh] += __shfl_xor_sync(0xffffffffu, den[hh], o);
        inv[hh] = 1.f / fmaxf(den[hh], 1e-16f);
    }
    __syncwarp();

    // pass 2: branch-free fast loop (i < CAP), then rare spill loop
    constexpr int NF2 = F / 64;
    float2 acc[NF2];
    #pragma unroll
    for (int fc = 0; fc < NF2; fc++) acc[fc] = make_float2(0.f, 0.f);

    const int fast = (deg < CAP) ? deg : CAP;
    #pragma unroll 2
    for (int i = 0; i < fast; i++) {
        int s = shsrc[w][i];
        float al[H];
        #pragma unroll
        for (int hh = 0; hh < H; hh++) al[hh] = shex[w][i * H + hh] * inv[hh];
        const __half2* hr = (const __half2*)(h + (size_t)s * F);
        #pragma unroll
        for (int fc = 0; fc < NF2; fc++) {
            int hh = (fc * 64) / C;
            float2 v = __half22float2(hr[fc * 32 + lane]);
            acc[fc].x = fmaf(al[hh], v.x, acc[fc].x);
            acc[fc].y = fmaf(al[hh], v.y, acc[fc].y);
        }
    }
    for (int i = CAP; i < deg; i++) {
        int s = col[start + i];
        float esv[H];
        if (H == 4) {
            float4 e4 = *(const float4*)(es + s * 4);
            esv[0] = e4.x; esv[1] = e4.y; esv[2] = e4.z; esv[3] = e4.w;
        } else {
            #pragma unroll
            for (int hh = 0; hh < H; hh++) esv[hh] = es[s * H + hh];
        }
        float al[H];
        #pragma unroll
        for (int hh = 0; hh < H; hh++) {
            float v = esv[hh] + edv[hh];
            v = (v > 0.f) ? v : 0.2f * v;
            al[hh] = expf(v) * inv[hh];
        }
        const __half2* hr = (const __half2*)(h + (size_t)s * F);
        #pragma unroll
        for (int fc = 0; fc < NF2; fc++) {
            int hh = (fc * 64) / C;
            float2 v = __half22float2(hr[fc * 32 + lane]);
            acc[fc].x = fmaf(al[hh], v.x, acc[fc].x);
            acc[fc].y = fmaf(al[hh], v.y, acc[fc].y);
        }
    }

    #pragma unroll
    for (int fc = 0; fc < NF2; fc++) {
        int f = fc * 64 + lane * 2;
        float vx = acc[fc].x + bias[f];
        float vy = acc[fc].y + bias[f + 1];
        if (do_elu) {
            vx = (vx > 0.f) ? vx : expm1f(vx);
            vy = (vy > 0.f) ? vy : expm1f(vy);
        }
        *(__half2*)(out + (size_t)d * F + f) = __floats2half2_rn(vx, vy);
    }
}

// ================= fused pool + MLP readout =================
__global__ void pool_mlp_kernel(const __half* __restrict__ h, const int* __restrict__ gstart,
                                const float* __restrict__ mW0, const float* __restrict__ mb0,
                                const float* __restrict__ mW1, const float* __restrict__ mb1,
                                const float* __restrict__ mW2, const float* __restrict__ mb2,
                                float* __restrict__ out, int G) {
    __shared__ float p[128], y1[64], y2[32];
    int g = blockIdx.x, t = threadIdx.x;
    if (g >= G) return;
    int s = gstart[g], e = gstart[g + 1];
    float acc = 0.f;
    for (int n = s; n < e; n++) acc += __half2float(h[(size_t)n * 128 + t]);
    float c = fmaxf((float)(e - s), 1.0f);
    p[t] = acc / c;
    __syncthreads();
    if (t < 64) {
        float sum = mb0[t];
        #pragma unroll 8
        for (int i = 0; i < 128; i++) sum += p[i] * mW0[i * 64 + t];
        y1[t] = fmaxf(sum, 0.0f);
    }
    __syncthreads();
    if (t < 32) {
        float sum = mb1[t];
        #pragma unroll 8
        for (int i = 0; i < 64; i++) sum += y1[i] * mW1[i * 32 + t];
        y2[t] = fmaxf(sum, 0.0f);
    }
    __syncthreads();
    if (t < 4) {
        float sum = mb2[t];
        #pragma unroll
        for (int i = 0; i < 32; i++) sum += y2[i] * mW2[i * 4 + t];
        out[g * 4 + t] = sum;
    }
}

// ================= host orchestration =================
extern "C" void kernel_launch(void* const* d_in, const int* in_sizes, int n_in,
                              void* d_out, int out_size) {
    const float* x     = (const float*)d_in[0];
    const int*   ei    = (const int*)d_in[1];
    const int*   batch = (const int*)d_in[2];
    const float* W0  = (const float*)d_in[4];
    const float* as0 = (const float*)d_in[5];
    const float* ad0 = (const float*)d_in[6];
    const float* b0  = (const float*)d_in[7];
    const float* W1  = (const float*)d_in[8];
    const float* as1 = (const float*)d_in[9];
    const float* ad1 = (const float*)d_in[10];
    const float* b1  = (const float*)d_in[11];
    const float* W2  = (const float*)d_in[12];
    const float* as2 = (const float*)d_in[13];
    const float* ad2 = (const float*)d_in[14];
    const float* b2  = (const float*)d_in[15];
    const float* W3  = (const float*)d_in[16];
    const float* as3 = (const float*)d_in[17];
    const float* ad3 = (const float*)d_in[18];
    const float* b3  = (const float*)d_in[19];
    const float* mW0 = (const float*)d_in[20];
    const float* mb0 = (const float*)d_in[21];
    const float* mW1 = (const float*)d_in[22];
    const float* mb1 = (const float*)d_in[23];
    const float* mW2 = (const float*)d_in[24];
    const float* mb2 = (const float*)d_in[25];

    int N = in_sizes[0] / 64;
    int E = in_sizes[1] / 2;
    int G = out_size / 4;
    int Etot = E + N;

    __half *hA, *hB, *hC, *hX, *Wh;
    float *esrc, *edst;
    int *rowptr, *fill, *col, *blksum, *gstart;
    cudaGetSymbolAddress((void**)&hA, g_hA);
    cudaGetSymbolAddress((void**)&hB, g_hB);
    cudaGetSymbolAddress((void**)&hC, g_hC);
    cudaGetSymbolAddress((void**)&hX, g_hX);
    cudaGetSymbolAddress((void**)&Wh, g_Wh);
    cudaGetSymbolAddress((void**)&esrc, g_esrc);
    cudaGetSymbolAddress((void**)&edst, g_edst);
    cudaGetSymbolAddress((void**)&rowptr, g_rowptr);
    cudaGetSymbolAddress((void**)&fill,   g_fill);
    cudaGetSymbolAddress((void**)&col,    g_col);
    cudaGetSymbolAddress((void**)&blksum, g_blksum);
    cudaGetSymbolAddress((void**)&gstart, g_gstart);

    __half* W0h = Wh;
    __half* W1h = W0h + 64 * 256;
    __half* W2h = W1h + 256 * 256;
    __half* W3h = W2h + 256 * 256;

    static cudaStream_t s2 = nullptr;
    static cudaEvent_t evFork = nullptr, evJoin = nullptr;
    if (s2 == nullptr) {
        cudaStreamCreateWithFlags(&s2, cudaStreamNonBlocking);
        cudaEventCreateWithFlags(&evFork, cudaEventDisableTiming);
        cudaEventCreateWithFlags(&evJoin, cudaEventDisableTiming);
    }

    // ---- fork: CSR + gstart chain on s2 ----
    cudaEventRecord(evFork, 0);
    cudaStreamWaitEvent(s2, evFork, 0);

    cudaMemsetAsync(fill, 0, (size_t)N * sizeof(int), s2);
    count_edges_kernel<<<(E + 255) / 256, 256, 0, s2>>>(ei, fill, E);
    int nb = (N + 1023) / 1024;
    scan_block_kernel<<<nb, 256, 0, s2>>>(fill, rowptr, blksum, N);
    scan_sums_kernel<<<1, 256, 0, s2>>>(blksum, nb);
    add_off_fill_kernel<<<(N + 255) / 256, 256, 0, s2>>>(rowptr, blksum, fill, N, Etot);
    fill_kernel<<<(Etot + 255) / 256, 256, 0, s2>>>(ei, fill, col, E, N);
    gstart_kernel<<<(N + 256) / 256, 256, 0, s2>>>(batch, gstart, N, G);
    cudaEventRecord(evJoin, s2);

    // ---- main stream: conversions + layer-0 GEMM ----
    f2h_kernel<<<(N * 64 / 4 + 255) / 256, 256>>>(x, hX, N * 64 / 4);
    wconv_kernel<<<(45056 + 255) / 256, 256>>>(W0, W1, W2, W3, Wh);

    int gy = (N + 127) / 128;
    gemm_fp16_scores_kernel<<<dim3(2, gy), 256>>>(hX, W0h, hA, N, 64, 256, as0, ad0, esrc, edst, 4, 64, 1);

    cudaStreamWaitEvent(0, evJoin, 0);

    gat_gather_kernel<4, 64><<<(N + 7) / 8, 256>>>(hA, esrc, edst, rowptr, col, b0, hB, N, 1);
    // ---- layer 1 ----
    gemm_fp16_scores_kernel<<<dim3(2, gy), 256>>>(hB, W1h, hA, N, 256, 256, as1, ad1, esrc, edst, 4, 64, 1);
    gat_gather_kernel<4, 64><<<(N + 7) / 8, 256>>>(hA, esrc, edst, rowptr, col, b1, hC, N, 1);
    // ---- layer 2 ----
    gemm_fp16_scores_kernel<<<dim3(2, gy), 256>>>(hC, W2h, hA, N, 256, 256, as2, ad2, esrc, edst, 4, 64, 1);
    gat_gather_kernel<4, 64><<<(N + 7) / 8, 256>>>(hA, esrc, edst, rowptr, col, b2, hB, N, 1);
    // ---- layer 3 ----
    gemm_fp16_scores_kernel<<<dim3(1, gy), 256>>>(hB, W3h, hA, N, 256, 128, as3, ad3, esrc, edst, 1, 128, 0);
    gat_gather_kernel<1, 128><<<(N + 7) / 8, 256>>>(hA, esrc, edst, rowptr, col, b3, hC, N, 0);

    // ---- fused pool + MLP ----
    pool_mlp_kernel<<<G, 128>>>(hC, gstart, mW0, mb0, mW1, mb1, mW2, mb2, (float*)d_out, G);
}

// round 17
// speedup vs baseline: 1.0219x; 1.0219x over previous
#include <cuda_runtime.h>
#include <cuda_fp16.h>
#include <math.h>
#include <float.h>
#include <stdint.h>

#define NMAX 100000
#define EMAX 400000
#define ETOTMAX (EMAX + NMAX)
#define GMAX 4096
#define FMAX 256

// ---------------- scratch ----------------
__device__ __half g_hA[NMAX * FMAX];
__device__ __half g_hB[NMAX * FMAX];
__device__ __half g_hC[NMAX * FMAX];
__device__ __half g_hX[NMAX * 64];
__device__ __half g_Wh[64*256 + 256*256 + 256*256 + 256*128];
__device__ float g_esrc[NMAX * 4];
__device__ float g_edst[NMAX * 4];
__device__ int g_rowptr[NMAX + 1];
__device__ int g_fill[NMAX];
__device__ int g_col[ETOTMAX];
__device__ int g_blksum[512];
__device__ int g_gstart[GMAX + 1];

// ================= helpers =================
__device__ __forceinline__ uint32_t smem_u32(const void* p) {
    uint32_t a;
    asm("{ .reg .u64 t; cvta.to.shared.u64 t, %1; cvt.u32.u64 %0, t; }" : "=r"(a) : "l"(p));
    return a;
}
__device__ __forceinline__ void ldsm_x4(uint32_t* r, uint32_t addr) {
    asm volatile("ldmatrix.sync.aligned.m8n8.x4.shared.b16 {%0,%1,%2,%3}, [%4];"
                 : "=r"(r[0]), "=r"(r[1]), "=r"(r[2]), "=r"(r[3]) : "r"(addr));
}
__device__ __forceinline__ void ldsm_x4_t(uint32_t* r, uint32_t addr) {
    asm volatile("ldmatrix.sync.aligned.m8n8.x4.trans.shared.b16 {%0,%1,%2,%3}, [%4];"
                 : "=r"(r[0]), "=r"(r[1]), "=r"(r[2]), "=r"(r[3]) : "r"(addr));
}
__device__ __forceinline__ void mma_fp16(float* c, const uint32_t* a, const uint32_t* b) {
    asm volatile(
        "mma.sync.aligned.m16n8k16.row.col.f32.f16.f16.f32 "
        "{%0,%1,%2,%3}, {%4,%5,%6,%7}, {%8,%9}, {%0,%1,%2,%3};"
        : "+f"(c[0]), "+f"(c[1]), "+f"(c[2]), "+f"(c[3])
        : "r"(a[0]), "r"(a[1]), "r"(a[2]), "r"(a[3]), "r"(b[0]), "r"(b[1]));
}
__device__ __forceinline__ void cp16z(uint32_t s, const void* g, bool ok) {
    int sz = ok ? 16 : 0;
    asm volatile("cp.async.cg.shared.global [%0], [%1], 16, %2;" :: "r"(s), "l"(g), "r"(sz));
}
__device__ __forceinline__ void cp_commit() { asm volatile("cp.async.commit_group;"); }
template<int W> __device__ __forceinline__ void cp_wait() {
    asm volatile("cp.async.wait_group %0;" :: "n"(W));
}

// ============ combined fp32->fp16 conversion: x + all four weights ============
__global__ void conv_all_kernel(const float* __restrict__ x, __half* __restrict__ hx, int nx4,
                                const float* __restrict__ W0, const float* __restrict__ W1,
                                const float* __restrict__ W2, const float* __restrict__ W3,
                                __half* __restrict__ wh) {
    int t = blockIdx.x * blockDim.x + threadIdx.x;
    const float* src;
    __half* dst;
    int idx;
    if (t < nx4) { src = x; dst = hx; idx = t; }
    else {
        int u = t - nx4;
        if (u >= 45056) return;
        dst = wh; idx = u;
        if (u < 4096) { src = W0; }
        else if (u < 20480) { src = W1; idx = u - 4096; dst = wh + 4096 * 4; }
        else if (u < 36864) { src = W2; idx = u - 20480; dst = wh + 20480 * 4; }
        else { src = W3; idx = u - 36864; dst = wh + 36864 * 4; }
        float4 v = *(const float4*)(src + idx * 4);
        __half2 a = __floats2half2_rn(v.x, v.y);
        __half2 b = __floats2half2_rn(v.z, v.w);
        *(uint2*)(dst + idx * 4) = make_uint2(*(uint32_t*)&a, *(uint32_t*)&b);
        return;
    }
    float4 v = *(const float4*)(src + idx * 4);
    __half2 a = __floats2half2_rn(v.x, v.y);
    __half2 b = __floats2half2_rn(v.z, v.w);
    *(uint2*)(dst + idx * 4) = make_uint2(*(uint32_t*)&a, *(uint32_t*)&b);
}

// ================= CSR build =================
__global__ void count_edges_kernel(const int* __restrict__ ei, int* __restrict__ cnt, int E) {
    int t = blockIdx.x * blockDim.x + threadIdx.x;
    if (t < E) atomicAdd(&cnt[ei[E + t]], 1);
}
__global__ void scan_block_kernel(const int* __restrict__ in, int* __restrict__ out,
                                  int* __restrict__ blksum, int n) {
    __shared__ int wsum[8];
    int t = threadIdx.x, blk = blockIdx.x;
    int base = blk * 1024 + t * 4;
    int v0 = (base + 0 < n) ? in[base + 0] : 0;
    int v1 = (base + 1 < n) ? in[base + 1] : 0;
    int v2 = (base + 2 < n) ? in[base + 2] : 0;
    int v3 = (base + 3 < n) ? in[base + 3] : 0;
    int tsum = v0 + v1 + v2 + v3;
    int lane = t & 31, w = t >> 5;
    int x = tsum;
    #pragma unroll
    for (int o = 1; o < 32; o <<= 1) {
        int y = __shfl_up_sync(0xffffffffu, x, o);
        if (lane >= o) x += y;
    }
    if (lane == 31) wsum[w] = x;
    __syncthreads();
    if (t < 8) {
        int y = wsum[t];
        #pragma unroll
        for (int o = 1; o < 8; o <<= 1) {
            int z = __shfl_up_sync(0xffu, y, o);
            if (t >= o) y += z;
        }
        wsum[t] = y;
    }
    __syncthreads();
    int woff = (w > 0) ? wsum[w - 1] : 0;
    int excl = woff + x - tsum;
    if (base + 0 < n) out[base + 0] = excl;
    if (base + 1 < n) out[base + 1] = excl + v0;
    if (base + 2 < n) out[base + 2] = excl + v0 + v1;
    if (base + 3 < n) out[base + 3] = excl + v0 + v1 + v2;
    if (t == 255) blksum[blk] = wsum[7];
}
__global__ void scan_sums_kernel(int* __restrict__ blksum, int nb) {
    __shared__ int sh[512];
    int t = threadIdx.x;
    int v = (t < nb) ? blksum[t] : 0;
    sh[t] = v;
    __syncthreads();
    for (int o = 1; o < 256; o <<= 1) {
        int y = (t >= o) ? sh[t - o] : 0;
        __syncthreads();
        sh[t] += y;
        __syncthreads();
    }
    if (t < nb) blksum[t] = sh[t] - v;
}
__global__ void add_off_fill_kernel(int* __restrict__ out, const int* __restrict__ blksum,
                                    int* __restrict__ fill, int n, int tail_val) {
    int t = blockIdx.x * blockDim.x + threadIdx.x;
    if (t < n) {
        int v = out[t] + blksum[t >> 10] + t;
        out[t] = v;
        fill[t] = v;
    }
    if (t == 0) out[n] = tail_val;
}
__global__ void fill_kernel(const int* __restrict__ ei, int* __restrict__ fill,
                            int* __restrict__ col, int E, int N) {
    int t = blockIdx.x * blockDim.x + threadIdx.x;
    int Etot = E + N;
    if (t >= Etot) return;
    int s, d;
    if (t < E) { s = ei[t]; d = ei[E + t]; } else { s = d = t - E; }
    int pos = atomicAdd(&fill[d], 1);
    col[pos] = s;
}
__global__ void gstart_kernel(const int* __restrict__ batch, int* __restrict__ gstart,
                              int N, int G) {
    int n = blockIdx.x * blockDim.x + threadIdx.x;
    if (n > N) return;
    int b = (n < N) ? batch[n] : G;
    int pb = (n > 0) ? batch[n - 1] : -1;
    for (int g = pb + 1; g <= b; g++) gstart[g] = n;
}

// ================= FP16 mma GEMM (cp.async 3-stage) + fused score epilogue ====
#define A_STRIDE 40
#define B_STRIDE 136
#define A_STAGE_BYTES (128 * A_STRIDE * 2)
#define B_STAGE_BYTES (32 * B_STRIDE * 2)
__global__ void __launch_bounds__(256, 2)
gemm_fp16_scores_kernel(const __half* __restrict__ A, const __half* __restrict__ B,
                        __half* __restrict__ C, int M, int K, int Ncol,
                        const float* __restrict__ a_s, const float* __restrict__ a_d,
                        float* __restrict__ esrc, float* __restrict__ edst,
                        int H, int Chead, int exclusive) {
    __shared__ __align__(16) __half sA[3][128 * A_STRIDE];
    __shared__ __align__(16) __half sB[3][32 * B_STRIDE];
    __shared__ float sred_ps[128], sred_pd[128];

    const int tid = threadIdx.x;
    const int bm = blockIdx.y * 128;
    const int bn = blockIdx.x * 128;
    const int warp = tid >> 5, lane = tid & 31;
    const int g = lane >> 2, tg = lane & 3;
    const int warp_m = (warp & 3) * 32;
    const int warp_n = (warp >> 2) * 64;

    const int a0 = tid, a1 = tid + 256;
    const int ar0 = a0 >> 2, ac0 = (a0 & 3) * 8;
    const int ar1 = a1 >> 2, ac1 = (a1 & 3) * 8;
    const bool aok0 = (bm + ar0) < M, aok1 = (bm + ar1) < M;
    const int br0 = a0 >> 4, bc0 = (a0 & 15) * 8;
    const int br1 = a1 >> 4, bc1 = (a1 & 15) * 8;

    const uint32_t sA_u = smem_u32(sA);
    const uint32_t sB_u = smem_u32(sB);
    const uint32_t aS0 = sA_u + (ar0 * A_STRIDE + ac0) * 2;
    const uint32_t aS1 = sA_u + (ar1 * A_STRIDE + ac1) * 2;
    const uint32_t bS0 = sB_u + (br0 * B_STRIDE + bc0) * 2;
    const uint32_t bS1 = sB_u + (br1 * B_STRIDE + bc1) * 2;

    const __half* Ag0 = A + (size_t)(bm + ar0) * K + ac0;
    const __half* Ag1 = A + (size_t)(bm + ar1) * K + ac1;
    const __half* Bg0 = B + (size_t)br0 * Ncol + bn + bc0;
    const __half* Bg1 = B + (size_t)br1 * Ncol + bn + bc1;

    const int nT = K >> 5;

    #define ISSUE_TILE(t_, st_) do { \
        int koff_ = (t_) * 32; \
        uint32_t ao_ = (st_) * (uint32_t)A_STAGE_BYTES; \
        uint32_t bo_ = (st_) * (uint32_t)B_STAGE_BYTES; \
        cp16z(aS0 + ao_, Ag0 + koff_, aok0); \
        cp16z(aS1 + ao_, Ag1 + koff_, aok1); \
        cp16z(bS0 + bo_, Bg0 + (size_t)koff_ * Ncol, true); \
        cp16z(bS1 + bo_, Bg1 + (size_t)koff_ * Ncol, true); \
        cp_commit(); \
    } while (0)

    ISSUE_TILE(0, 0);
    if (nT > 1) ISSUE_TILE(1, 1);

    float acc[2][8][4];
    #pragma unroll
    for (int mt = 0; mt < 2; mt++)
        #pragma unroll
        for (int nt = 0; nt < 8; nt++)
            #pragma unroll
            for (int r = 0; r < 4; r++) acc[mt][nt][r] = 0.f;

    const uint32_t a_frag0 = sA_u + ((warp_m + (lane & 15)) * A_STRIDE + (lane >> 4) * 8) * 2;
    const uint32_t b_frag0 = sB_u + ((((lane >> 3) & 1) * 8 + (lane & 7)) * B_STRIDE
                                     + warp_n + (lane >> 4) * 8) * 2;

    int stage = 0;
    for (int t = 0; t < nT; t++) {
        if (t + 2 < nT) {
            ISSUE_TILE(t + 2, (stage + 2) % 3);
            cp_wait<2>();
        } else if (t + 1 < nT) {
            cp_wait<1>();
        } else {
            cp_wait<0>();
        }
        __syncthreads();

        const uint32_t aoff = stage * (uint32_t)A_STAGE_BYTES;
        const uint32_t boff = stage * (uint32_t)B_STAGE_BYTES;
        #pragma unroll
        for (int kk = 0; kk < 2; kk++) {
            uint32_t afr[2][4], bfr[8][2];
            #pragma unroll
            for (int mt = 0; mt < 2; mt++) {
                ldsm_x4(afr[mt], a_frag0 + aoff + (mt * 16 * A_STRIDE + kk * 16) * 2);
            }
            #pragma unroll
            for (int p = 0; p < 4; p++) {
                uint32_t r[4];
                ldsm_x4_t(r, b_frag0 + boff + (kk * 16 * B_STRIDE + p * 16) * 2);
                bfr[2 * p][0] = r[0]; bfr[2 * p][1] = r[1];
                bfr[2 * p + 1][0] = r[2]; bfr[2 * p + 1][1] = r[3];
            }
            #pragma unroll
            for (int mt = 0; mt < 2; mt++)
                #pragma unroll
                for (int nt = 0; nt < 8; nt++)
                    mma_fp16(acc[mt][nt], afr[mt], bfr[nt]);
        }
        __syncthreads();
        stage = (stage + 1) % 3;
    }
    #undef ISSUE_TILE

    const int hh = (bn + warp_n) / Chead;
    #pragma unroll
    for (int mt = 0; mt < 2; mt++) {
        int r0 = bm + warp_m + mt * 16 + g;
        int r1 = r0 + 8;
        float ps0 = 0.f, pd0 = 0.f, ps1 = 0.f, pd1 = 0.f;
        #pragma unroll
        for (int nt = 0; nt < 8; nt++) {
            int c = bn + warp_n + nt * 8 + 2 * tg;
            float asv0 = a_s[c], asv1 = a_s[c + 1];
            float adv0 = a_d[c], adv1 = a_d[c + 1];
            ps0 += acc[mt][nt][0] * asv0 + acc[mt][nt][1] * asv1;
            pd0 += acc[mt][nt][0] * adv0 + acc[mt][nt][1] * adv1;
            ps1 += acc[mt][nt][2] * asv0 + acc[mt][nt][3] * asv1;
            pd1 += acc[mt][nt][2] * adv0 + acc[mt][nt][3] * adv1;
            if (r0 < M) *(__half2*)(C + (size_t)r0 * Ncol + c) = __floats2half2_rn(acc[mt][nt][0], acc[mt][nt][1]);
            if (r1 < M) *(__half2*)(C + (size_t)r1 * Ncol + c) = __floats2half2_rn(acc[mt][nt][2], acc[mt][nt][3]);
        }
        #pragma unroll
        for (int o = 1; o < 4; o <<= 1) {
            ps0 += __shfl_xor_sync(0xffffffffu, ps0, o);
            pd0 += __shfl_xor_sync(0xffffffffu, pd0, o);
            ps1 += __shfl_xor_sync(0xffffffffu, ps1, o);
            pd1 += __shfl_xor_sync(0xffffffffu, pd1, o);
        }
        if (exclusive) {
            if (tg == 0) {
                if (r0 < M) { esrc[r0 * H + hh] = ps0; edst[r0 * H + hh] = pd0; }
                if (r1 < M) { esrc[r1 * H + hh] = ps1; edst[r1 * H + hh] = pd1; }
            }
        } else {
            if (tg == 0 && warp < 4) {
                sred_ps[r0 - bm] = ps0; sred_pd[r0 - bm] = pd0;
                sred_ps[r1 - bm] = ps1; sred_pd[r1 - bm] = pd1;
            }
            __syncthreads();
            if (tg == 0 && warp >= 4) {
                if (r0 < M) {
                    esrc[r0 * H + hh] = ps0 + sred_ps[r0 - bm];
                    edst[r0 * H + hh] = pd0 + sred_pd[r0 - bm];
                }
                if (r1 < M) {
                    esrc[r1 * H + hh] = ps1 + sred_ps[r1 - bm];
                    edst[r1 * H + hh] = pd1 + sred_pd[r1 - bm];
                }
            }
            __syncthreads();
        }
    }
}

// ================= fused gather (R13 version — known good) =================
template<int H, int C>
__global__ void gat_gather_kernel(const __half* __restrict__ h,
                                  const float* __restrict__ es, const float* __restrict__ ed,
                                  const int* __restrict__ rowptr, const int* __restrict__ col,
                                  const float* __restrict__ bias, __half* __restrict__ out,
                                  int N, int do_elu) {
    constexpr int F = H * C;
    constexpr int CAP = 64;
    constexpr int NW = 8;
    __shared__ float shex[NW][CAP * H];
    __shared__ int   shsrc[NW][CAP];
    const int w = threadIdx.x >> 5, lane = threadIdx.x & 31;
    const int d = blockIdx.x * NW + w;
    if (d >= N) return;
    const int start = rowptr[d];
    const int deg = rowptr[d + 1] - start;

    float edv[H];
    #pragma unroll
    for (int hh = 0; hh < H; hh++) edv[hh] = ed[d * H + hh];

    float den[H];
    #pragma unroll
    for (int hh = 0; hh < H; hh++) den[hh] = 0.f;
    for (int i0 = 0; i0 < deg; i0 += 32) {
        int i = i0 + lane;
        if (i < deg) {
            int s = col[start + i];
            if (i < CAP) shsrc[w][i] = s;
            float esv[H];
            if (H == 4) {
                float4 e4 = *(const float4*)(es + s * 4);
                esv[0] = e4.x; esv[1] = e4.y; esv[2] = e4.z; esv[3] = e4.w;
            } else {
                #pragma unroll
                for (int hh = 0; hh < H; hh++) esv[hh] = es[s * H + hh];
            }
            #pragma unroll
            for (int hh = 0; hh < H; hh++) {
                float v = esv[hh] + edv[hh];
                v = (v > 0.f) ? v : 0.2f * v;
                float ex = expf(v);
                if (i < CAP) shex[w][i * H + hh] = ex;
                den[hh] += ex;
            }
        }
    }
    float inv[H];
    #pragma unroll
    for (int hh = 0; hh < H; hh++) {
        #pragma unroll
        for (int o = 16; o; o >>= 1) den[hh] += __shfl_xor_sync(0xffffffffu, den[hh], o);
        inv[hh] = 1.f / fmaxf(den[hh], 1e-16f);
    }
    __syncwarp();

    constexpr int NF2 = F / 64;
    float2 acc[NF2];
    #pragma unroll
    for (int fc = 0; fc < NF2; fc++) acc[fc] = make_float2(0.f, 0.f);
    for (int i = 0; i < deg; i++) {
        int s;
        float al[H];
        if (i < CAP) {
            s = shsrc[w][i];
            #pragma unroll
            for (int hh = 0; hh < H; hh++) al[hh] = shex[w][i * H + hh] * inv[hh];
        } else {
            s = col[start + i];
            float esv[H];
            if (H == 4) {
                float4 e4 = *(const float4*)(es + s * 4);
                esv[0] = e4.x; esv[1] = e4.y; esv[2] = e4.z; esv[3] = e4.w;
            } else {
                #pragma unroll
                for (int hh = 0; hh < H; hh++) esv[hh] = es[s * H + hh];
            }
            #pragma unroll
            for (int hh = 0; hh < H; hh++) {
                float v = esv[hh] + edv[hh];
                v = (v > 0.f) ? v : 0.2f * v;
                al[hh] = expf(v) * inv[hh];
            }
        }
        const __half2* hr = (const __half2*)(h + (size_t)s * F);
        #pragma unroll
        for (int fc = 0; fc < NF2; fc++) {
            int hh = (fc * 64) / C;
            float2 v = __half22float2(hr[fc * 32 + lane]);
            acc[fc].x = fmaf(al[hh], v.x, acc[fc].x);
            acc[fc].y = fmaf(al[hh], v.y, acc[fc].y);
        }
    }
    #pragma unroll
    for (int fc = 0; fc < NF2; fc++) {
        int f = fc * 64 + lane * 2;
        float vx = acc[fc].x + bias[f];
        float vy = acc[fc].y + bias[f + 1];
        if (do_elu) {
            vx = (vx > 0.f) ? vx : expm1f(vx);
            vy = (vy > 0.f) ? vy : expm1f(vy);
        }
        *(__half2*)(out + (size_t)d * F + f) = __floats2half2_rn(vx, vy);
    }
}

// ================= fused pool + MLP readout =================
__global__ void pool_mlp_kernel(const __half* __restrict__ h, const int* __restrict__ gstart,
                                const float* __restrict__ mW0, const float* __restrict__ mb0,
                                const float* __restrict__ mW1, const float* __restrict__ mb1,
                                const float* __restrict__ mW2, const float* __restrict__ mb2,
                                float* __restrict__ out, int G) {
    __shared__ float p[128], y1[64], y2[32];
    int g = blockIdx.x, t = threadIdx.x;
    if (g >= G) return;
    int s = gstart[g], e = gstart[g + 1];
    float acc = 0.f;
    for (int n = s; n < e; n++) acc += __half2float(h[(size_t)n * 128 + t]);
    float c = fmaxf((float)(e - s), 1.0f);
    p[t] = acc / c;
    __syncthreads();
    if (t < 64) {
        float sum = mb0[t];
        #pragma unroll 8
        for (int i = 0; i < 128; i++) sum += p[i] * mW0[i * 64 + t];
        y1[t] = fmaxf(sum, 0.0f);
    }
    __syncthreads();
    if (t < 32) {
        float sum = mb1[t];
        #pragma unroll 8
        for (int i = 0; i < 64; i++) sum += y1[i] * mW1[i * 32 + t];
        y2[t] = fmaxf(sum, 0.0f);
    }
    __syncthreads();
    if (t < 4) {
        float sum = mb2[t];
        #pragma unroll
        for (int i = 0; i < 32; i++) sum += y2[i] * mW2[i * 4 + t];
        out[g * 4 + t] = sum;
    }
}

// ================= host orchestration =================
extern "C" void kernel_launch(void* const* d_in, const int* in_sizes, int n_in,
                              void* d_out, int out_size) {
    const float* x     = (const float*)d_in[0];
    const int*   ei    = (const int*)d_in[1];
    const int*   batch = (const int*)d_in[2];
    const float* W0  = (const float*)d_in[4];
    const float* as0 = (const float*)d_in[5];
    const float* ad0 = (const float*)d_in[6];
    const float* b0  = (const float*)d_in[7];
    const float* W1  = (const float*)d_in[8];
    const float* as1 = (const float*)d_in[9];
    const float* ad1 = (const float*)d_in[10];
    const float* b1  = (const float*)d_in[11];
    const float* W2  = (const float*)d_in[12];
    const float* as2 = (const float*)d_in[13];
    const float* ad2 = (const float*)d_in[14];
    const float* b2  = (const float*)d_in[15];
    const float* W3  = (const float*)d_in[16];
    const float* as3 = (const float*)d_in[17];
    const float* ad3 = (const float*)d_in[18];
    const float* b3  = (const float*)d_in[19];
    const float* mW0 = (const float*)d_in[20];
    const float* mb0 = (const float*)d_in[21];
    const float* mW1 = (const float*)d_in[22];
    const float* mb1 = (const float*)d_in[23];
    const float* mW2 = (const float*)d_in[24];
    const float* mb2 = (const float*)d_in[25];

    int N = in_sizes[0] / 64;
    int E = in_sizes[1] / 2;
    int G = out_size / 4;
    int Etot = E + N;

    __half *hA, *hB, *hC, *hX, *Wh;
    float *esrc, *edst;
    int *rowptr, *fill, *col, *blksum, *gstart;
    cudaGetSymbolAddress((void**)&hA, g_hA);
    cudaGetSymbolAddress((void**)&hB, g_hB);
    cudaGetSymbolAddress((void**)&hC, g_hC);
    cudaGetSymbolAddress((void**)&hX, g_hX);
    cudaGetSymbolAddress((void**)&Wh, g_Wh);
    cudaGetSymbolAddress((void**)&esrc, g_esrc);
    cudaGetSymbolAddress((void**)&edst, g_edst);
    cudaGetSymbolAddress((void**)&rowptr, g_rowptr);
    cudaGetSymbolAddress((void**)&fill,   g_fill);
    cudaGetSymbolAddress((void**)&col,    g_col);
    cudaGetSymbolAddress((void**)&blksum, g_blksum);
    cudaGetSymbolAddress((void**)&gstart, g_gstart);

    __half* W0h = Wh;
    __half* W1h = W0h + 64 * 256;
    __half* W2h = W1h + 256 * 256;
    __half* W3h = W2h + 256 * 256;

    static cudaStream_t s2 = nullptr;
    static cudaEvent_t evFork = nullptr, evCSR = nullptr, evGst = nullptr;
    if (s2 == nullptr) {
        cudaStreamCreateWithFlags(&s2, cudaStreamNonBlocking);
        cudaEventCreateWithFlags(&evFork, cudaEventDisableTiming);
        cudaEventCreateWithFlags(&evCSR, cudaEventDisableTiming);
        cudaEventCreateWithFlags(&evGst, cudaEventDisableTiming);
    }

    // ---- fork: CSR chain on s2 (gstart after CSR event; only pool_mlp needs it) ----
    cudaEventRecord(evFork, 0);
    cudaStreamWaitEvent(s2, evFork, 0);

    cudaMemsetAsync(fill, 0, (size_t)N * sizeof(int), s2);
    count_edges_kernel<<<(E + 255) / 256, 256, 0, s2>>>(ei, fill, E);
    int nb = (N + 1023) / 1024;
    scan_block_kernel<<<nb, 256, 0, s2>>>(fill, rowptr, blksum, N);
    scan_sums_kernel<<<1, 256, 0, s2>>>(blksum, nb);
    add_off_fill_kernel<<<(N + 255) / 256, 256, 0, s2>>>(rowptr, blksum, fill, N, Etot);
    fill_kernel<<<(Etot + 255) / 256, 256, 0, s2>>>(ei, fill, col, E, N);
    cudaEventRecord(evCSR, s2);
    gstart_kernel<<<(N + 256) / 256, 256, 0, s2>>>(batch, gstart, N, G);
    cudaEventRecord(evGst, s2);

    // ---- main stream: combined conversion + layer-0 GEMM ----
    int nx4 = N * 64 / 4;
    conv_all_kernel<<<(nx4 + 45056 + 255) / 256, 256>>>(x, hX, nx4, W0, W1, W2, W3, Wh);

    int gy = (N + 127) / 128;
    gemm_fp16_scores_kernel<<<dim3(2, gy), 256>>>(hX, W0h, hA, N, 64, 256, as0, ad0, esrc, edst, 4, 64, 1);

    cudaStreamWaitEvent(0, evCSR, 0);

    gat_gather_kernel<4, 64><<<(N + 7) / 8, 256>>>(hA, esrc, edst, rowptr, col, b0, hB, N, 1);
    // ---- layer 1 ----
    gemm_fp16_scores_kernel<<<dim3(2, gy), 256>>>(hB, W1h, hA, N, 256, 256, as1, ad1, esrc, edst, 4, 64, 1);
    gat_gather_kernel<4, 64><<<(N + 7) / 8, 256>>>(hA, esrc, edst, rowptr, col, b1, hC, N, 1);
    // ---- layer 2 ----
    gemm_fp16_scores_kernel<<<dim3(2, gy), 256>>>(hC, W2h, hA, N, 256, 256, as2, ad2, esrc, edst, 4, 64, 1);
    gat_gather_kernel<4, 64><<<(N + 7) / 8, 256>>>(hA, esrc, edst, rowptr, col, b2, hB, N, 1);
    // ---- layer 3: smem score reduction in GEMM epilogue ----
    gemm_fp16_scores_kernel<<<dim3(1, gy), 256>>>(hB, W3h, hA, N, 256, 128, as3, ad3, esrc, edst, 1, 128, 0);
    gat_gather_kernel<1, 128><<<(N + 7) / 8, 256>>>(hA, esrc, edst, rowptr, col, b3, hC, N, 0);

    // ---- fused pool + MLP (needs gstart) ----
    cudaStreamWaitEvent(0, evGst, 0);
    pool_mlp_kernel<<<G, 128>>>(hC, gstart, mW0, mb0, mW1, mb1, mW2, mb2, (float*)d_out, G);
}